// round 3
// baseline (speedup 1.0000x reference)
#include <cuda_runtime.h>
#include <cuda_fp16.h>
#include <cstdint>

#define IN_DIM  128
#define OUT_DIM 128
#define NHEADS  4
#define NEG_SLOPE 0.2f

#define N_MAX 50000
#define E_MAX 1600000
#define FULL 0xFFFFFFFFu
#define MAXC 4   // cached strips per lane: covers deg <= 128

// -------- device scratch (static: no allocation allowed) --------
__device__ float  g_hq   [N_MAX * NHEADS];
__device__ float  g_kact [N_MAX * NHEADS];
__device__ float  g_qagg [N_MAX * NHEADS];
__device__ __half g_hproj[(size_t)N_MAX * OUT_DIM];
__device__ int    g_cnt  [N_MAX];
__device__ int    g_off  [N_MAX + 1];
__device__ int    g_pos  [N_MAX];
__device__ int    g_bsum [256];
__device__ int    g_csr_col[E_MAX];

// ================= kernel 0: init (zero histogram) =================
__global__ __launch_bounds__(256) void init_kernel(int N) {
    int i = blockIdx.x * 256 + threadIdx.x;
    if (i < N) g_cnt[i] = 0;
}

// ================= kernel 1: projections =================
#define NPB 16
__global__ __launch_bounds__(128) void proj_kernel(
    const float* __restrict__ x,
    const float* __restrict__ Wq, const float* __restrict__ Wk,
    const float* __restrict__ Wl, const float* __restrict__ bl, int N)
{
    __shared__ float xs[NPB * IN_DIM];
    const int t = threadIdx.x;
    const int base = blockIdx.x * NPB;
    const int nn = min(NPB, N - base);
    if (nn <= 0) return;

    {
        const float4* xg = (const float4*)(x + (size_t)base * IN_DIM);
        float4* xs4 = (float4*)xs;
        const int tot4 = nn * (IN_DIM / 4);
        for (int i = t; i < tot4; i += 128) xs4[i] = xg[i];
    }
    __syncthreads();

    // per-head q/k projections: t = n2*8 + h
    {
        const int n2 = t >> 3;
        const int h  = t & 7;
        if (n2 < nn) {
            const float* wrow = (h < 4) ? (Wq + h * IN_DIM) : (Wk + (h - 4) * IN_DIM);
            const float4* w4 = (const float4*)wrow;
            const float4* xr = (const float4*)(xs + n2 * IN_DIM);
            float d = 0.0f;
            #pragma unroll
            for (int k = 0; k < IN_DIM / 4; k++) {
                float4 w = w4[k]; float4 xv = xr[k];
                d += w.x * xv.x + w.y * xv.y + w.z * xv.z + w.w * xv.w;
            }
            const int node = base + n2;
            if (h < 4) g_hq[node * NHEADS + h] = d;
            else       g_kact[node * NHEADS + (h - 4)] = (d >= 0.0f) ? d : NEG_SLOPE * d;
        }
    }

    float acc[NPB];
    #pragma unroll
    for (int n = 0; n < NPB; n++) acc[n] = 0.0f;

    const float4* wl4 = (const float4*)(Wl + (size_t)t * IN_DIM);
    #pragma unroll 4
    for (int k = 0; k < IN_DIM / 4; k++) {
        float4 w = wl4[k];
        #pragma unroll
        for (int n = 0; n < NPB; n++) {
            float4 xv = ((const float4*)(xs + n * IN_DIM))[k];
            acc[n] += w.x * xv.x + w.y * xv.y + w.z * xv.z + w.w * xv.w;
        }
    }
    const float b = bl[t];
    for (int n = 0; n < nn; n++)
        g_hproj[(size_t)(base + n) * OUT_DIM + t] = __float2half_rn(acc[n] + b);
}

// ================= kernel 2: histogram of rows =================
__global__ __launch_bounds__(256) void hist_kernel(const int* __restrict__ rows, int E) {
    int e = blockIdx.x * 256 + threadIdx.x;
    if (e < E) atomicAdd(&g_cnt[rows[e]], 1);
}

// ================= scan (3 stages) =================
__device__ __forceinline__ int warp_incl_scan(int v, int lane) {
    #pragma unroll
    for (int d = 1; d < 32; d <<= 1) {
        int t = __shfl_up_sync(FULL, v, d);
        if (lane >= d) v += t;
    }
    return v;
}

__global__ __launch_bounds__(256) void scan1_kernel(int N) {
    int i = blockIdx.x * 256 + threadIdx.x;
    int lane = threadIdx.x & 31, wid = threadIdx.x >> 5;
    int v = (i < N) ? g_cnt[i] : 0;
    int s = warp_incl_scan(v, lane);
    __shared__ int wsum[8];
    if (lane == 31) wsum[wid] = s;
    __syncthreads();
    if (wid == 0) {
        int ws = (lane < 8) ? wsum[lane] : 0;
        #pragma unroll
        for (int d = 1; d < 8; d <<= 1) {
            int t = __shfl_up_sync(FULL, ws, d);
            if (lane >= d) ws += t;
        }
        if (lane < 8) wsum[lane] = ws;
    }
    __syncthreads();
    int excl = s - v + (wid > 0 ? wsum[wid - 1] : 0);
    if (i < N) g_off[i] = excl;
    if (threadIdx.x == 255) g_bsum[blockIdx.x] = excl + v;
}

__global__ __launch_bounds__(256) void scan2_kernel(int nb) {
    int i = threadIdx.x;
    int lane = i & 31, wid = i >> 5;
    int v = (i < nb) ? g_bsum[i] : 0;
    int s = warp_incl_scan(v, lane);
    __shared__ int wsum[8];
    if (lane == 31) wsum[wid] = s;
    __syncthreads();
    if (wid == 0) {
        int ws = (lane < 8) ? wsum[lane] : 0;
        #pragma unroll
        for (int d = 1; d < 8; d <<= 1) {
            int t = __shfl_up_sync(FULL, ws, d);
            if (lane >= d) ws += t;
        }
        if (lane < 8) wsum[lane] = ws;
    }
    __syncthreads();
    int excl = s - v + (wid > 0 ? wsum[wid - 1] : 0);
    if (i < nb) g_bsum[i] = excl;
}

__global__ __launch_bounds__(256) void scan3_kernel(int N, int E) {
    int i = blockIdx.x * 256 + threadIdx.x;
    if (i < N) {
        int o = g_off[i] + g_bsum[i >> 8];
        g_off[i] = o;
        g_pos[i] = o;
    }
    if (i == 0) g_off[N] = E;
}

// ================= kernel: scatter edges into CSR =================
__global__ __launch_bounds__(256) void scatter_kernel(
    const int* __restrict__ rows, const int* __restrict__ cols, int E)
{
    int e = blockIdx.x * 256 + threadIdx.x;
    if (e >= E) return;
    int r = rows[e];
    int p = atomicAdd(&g_pos[r], 1);
    g_csr_col[p] = cols[e];
}

// ================= kernel: q_agg via CSR (no atomics) =================
__global__ __launch_bounds__(256) void qagg_csr_kernel(int N) {
    int w = (blockIdx.x * 256 + threadIdx.x) >> 5;
    int lane = threadIdx.x & 31;
    if (w >= N) return;
    int beg = g_off[w], end = g_off[w + 1];
    float4 acc = {0.f, 0.f, 0.f, 0.f};
    for (int e = beg + lane; e < end; e += 32) {
        int c = __ldg(g_csr_col + e);
        float4 v = __ldg(((const float4*)g_hq) + c);
        acc.x += v.x; acc.y += v.y; acc.z += v.z; acc.w += v.w;
    }
    #pragma unroll
    for (int d = 16; d; d >>= 1) {
        acc.x += __shfl_xor_sync(FULL, acc.x, d);
        acc.y += __shfl_xor_sync(FULL, acc.y, d);
        acc.z += __shfl_xor_sync(FULL, acc.z, d);
        acc.w += __shfl_xor_sync(FULL, acc.w, d);
    }
    if (lane == 0) ((float4*)g_qagg)[w] = acc;
}

// ================= fused attention + aggregation (warp per node) ======
__device__ __forceinline__ void agg_strip(float4& acc, float a, int c, int lane, int cnt) {
    const uint2* hp = (const uint2*)g_hproj;
    #pragma unroll 4
    for (int j = 0; j < 32; j++) {
        if (j >= cnt) break;
        float aj = __shfl_sync(FULL, a, j);
        int   cj = __shfl_sync(FULL, c, j);
        uint2 u = __ldg(hp + (size_t)cj * 32 + lane);
        float2 f0 = __half22float2(*reinterpret_cast<__half2*>(&u.x));
        float2 f1 = __half22float2(*reinterpret_cast<__half2*>(&u.y));
        acc.x = fmaf(aj, f0.x, acc.x);
        acc.y = fmaf(aj, f0.y, acc.y);
        acc.z = fmaf(aj, f1.x, acc.z);
        acc.w = fmaf(aj, f1.y, acc.w);
    }
}

__global__ __launch_bounds__(256) void attn_agg_kernel(float* __restrict__ out, int N) {
    int node = (blockIdx.x * 256 + threadIdx.x) >> 5;
    int lane = threadIdx.x & 31;
    if (node >= N) return;
    const int beg = g_off[node], end = g_off[node + 1];
    const int deg = end - beg;

    float4* outp = ((float4*)out) + (size_t)node * (OUT_DIM / 4) + lane;
    if (deg == 0) { float4 z = {0.f,0.f,0.f,0.f}; *outp = z; return; }

    const float4 ka = ((const float4*)g_kact)[node];
    const int nstr = (deg + 31) >> 5;
    float4 acc = {0.f, 0.f, 0.f, 0.f};

    if (nstr <= MAXC) {
        // ---- fast path: cache q-gathers (and later exp values) in registers
        float4 qc[MAXC];
        int    cc[MAXC];
        #pragma unroll
        for (int s = 0; s < MAXC; s++) {
            qc[s] = make_float4(0.f,0.f,0.f,0.f); cc[s] = 0;
            if (s < nstr) {
                int e = beg + s * 32 + lane;
                if (e < end) {
                    cc[s] = __ldg(g_csr_col + e);
                    qc[s] = __ldg(((const float4*)g_qagg) + cc[s]);
                }
            }
        }
        // per-head max over valid edges
        float4 mx = {-3.4e38f, -3.4e38f, -3.4e38f, -3.4e38f};
        #pragma unroll
        for (int s = 0; s < MAXC; s++) {
            if (s < nstr) {
                int e = beg + s * 32 + lane;
                if (e < end) {
                    mx.x = fmaxf(mx.x, ka.x * qc[s].x);
                    mx.y = fmaxf(mx.y, ka.y * qc[s].y);
                    mx.z = fmaxf(mx.z, ka.z * qc[s].z);
                    mx.w = fmaxf(mx.w, ka.w * qc[s].w);
                }
            }
        }
        #pragma unroll
        for (int d = 16; d; d >>= 1) {
            mx.x = fmaxf(mx.x, __shfl_xor_sync(FULL, mx.x, d));
            mx.y = fmaxf(mx.y, __shfl_xor_sync(FULL, mx.y, d));
            mx.z = fmaxf(mx.z, __shfl_xor_sync(FULL, mx.z, d));
            mx.w = fmaxf(mx.w, __shfl_xor_sync(FULL, mx.w, d));
        }
        // exp (stored back into qc) + sum
        float4 sm = {0.f, 0.f, 0.f, 0.f};
        #pragma unroll
        for (int s = 0; s < MAXC; s++) {
            if (s < nstr) {
                int e = beg + s * 32 + lane;
                if (e < end) {
                    qc[s].x = __expf(ka.x * qc[s].x - mx.x);
                    qc[s].y = __expf(ka.y * qc[s].y - mx.y);
                    qc[s].z = __expf(ka.z * qc[s].z - mx.z);
                    qc[s].w = __expf(ka.w * qc[s].w - mx.w);
                    sm.x += qc[s].x; sm.y += qc[s].y; sm.z += qc[s].z; sm.w += qc[s].w;
                }
            }
        }
        #pragma unroll
        for (int d = 16; d; d >>= 1) {
            sm.x += __shfl_xor_sync(FULL, sm.x, d);
            sm.y += __shfl_xor_sync(FULL, sm.y, d);
            sm.z += __shfl_xor_sync(FULL, sm.z, d);
            sm.w += __shfl_xor_sync(FULL, sm.w, d);
        }
        float4 inv;
        inv.x = 0.25f * __fdividef(1.0f, sm.x + 1e-8f);
        inv.y = 0.25f * __fdividef(1.0f, sm.y + 1e-8f);
        inv.z = 0.25f * __fdividef(1.0f, sm.z + 1e-8f);
        inv.w = 0.25f * __fdividef(1.0f, sm.w + 1e-8f);

        #pragma unroll
        for (int s = 0; s < MAXC; s++) {
            if (s < nstr) {
                int base = beg + s * 32;
                float a = qc[s].x * inv.x + qc[s].y * inv.y + qc[s].z * inv.z + qc[s].w * inv.w;
                agg_strip(acc, a, cc[s], lane, min(32, end - base));
            }
        }
    } else {
        // ---- fallback: gather-based 3 passes (deg > 128, rare)
        float4 mx = {-3.4e38f, -3.4e38f, -3.4e38f, -3.4e38f};
        for (int e = beg + lane; e < end; e += 32) {
            int c = __ldg(g_csr_col + e);
            float4 q = __ldg(((const float4*)g_qagg) + c);
            mx.x = fmaxf(mx.x, ka.x * q.x);
            mx.y = fmaxf(mx.y, ka.y * q.y);
            mx.z = fmaxf(mx.z, ka.z * q.z);
            mx.w = fmaxf(mx.w, ka.w * q.w);
        }
        #pragma unroll
        for (int d = 16; d; d >>= 1) {
            mx.x = fmaxf(mx.x, __shfl_xor_sync(FULL, mx.x, d));
            mx.y = fmaxf(mx.y, __shfl_xor_sync(FULL, mx.y, d));
            mx.z = fmaxf(mx.z, __shfl_xor_sync(FULL, mx.z, d));
            mx.w = fmaxf(mx.w, __shfl_xor_sync(FULL, mx.w, d));
        }
        float4 sm = {0.f, 0.f, 0.f, 0.f};
        for (int e = beg + lane; e < end; e += 32) {
            int c = __ldg(g_csr_col + e);
            float4 q = __ldg(((const float4*)g_qagg) + c);
            sm.x += __expf(ka.x * q.x - mx.x);
            sm.y += __expf(ka.y * q.y - mx.y);
            sm.z += __expf(ka.z * q.z - mx.z);
            sm.w += __expf(ka.w * q.w - mx.w);
        }
        #pragma unroll
        for (int d = 16; d; d >>= 1) {
            sm.x += __shfl_xor_sync(FULL, sm.x, d);
            sm.y += __shfl_xor_sync(FULL, sm.y, d);
            sm.z += __shfl_xor_sync(FULL, sm.z, d);
            sm.w += __shfl_xor_sync(FULL, sm.w, d);
        }
        float4 inv;
        inv.x = 0.25f * __fdividef(1.0f, sm.x + 1e-8f);
        inv.y = 0.25f * __fdividef(1.0f, sm.y + 1e-8f);
        inv.z = 0.25f * __fdividef(1.0f, sm.z + 1e-8f);
        inv.w = 0.25f * __fdividef(1.0f, sm.w + 1e-8f);

        for (int base = beg; base < end; base += 32) {
            int e = base + lane;
            float a = 0.0f; int c = 0;
            if (e < end) {
                c = __ldg(g_csr_col + e);
                float4 q = __ldg(((const float4*)g_qagg) + c);
                a = __expf(ka.x * q.x - mx.x) * inv.x
                  + __expf(ka.y * q.y - mx.y) * inv.y
                  + __expf(ka.z * q.z - mx.z) * inv.z
                  + __expf(ka.w * q.w - mx.w) * inv.w;
            }
            agg_strip(acc, a, c, lane, min(32, end - base));
        }
    }

    // fused final leaky relu + single coalesced write
    acc.x = (acc.x >= 0.f) ? acc.x : NEG_SLOPE * acc.x;
    acc.y = (acc.y >= 0.f) ? acc.y : NEG_SLOPE * acc.y;
    acc.z = (acc.z >= 0.f) ? acc.z : NEG_SLOPE * acc.z;
    acc.w = (acc.w >= 0.f) ? acc.w : NEG_SLOPE * acc.w;
    *outp = acc;
}

// ================= launch =================
extern "C" void kernel_launch(void* const* d_in, const int* in_sizes, int n_in,
                              void* d_out, int out_size)
{
    const float* x  = (const float*)d_in[0];
    const int*   ei = (const int*)d_in[1];
    const float* Wq = (const float*)d_in[2];
    const float* Wk = (const float*)d_in[3];
    const float* Wl = (const float*)d_in[4];
    const float* bl = (const float*)d_in[5];
    float* out = (float*)d_out;

    const int N = in_sizes[0] / IN_DIM;
    const int E = in_sizes[1] / 2;
    const int* rows = ei;
    const int* cols = ei + E;
    const int nblocksN = (N + 255) / 256;

    init_kernel<<<nblocksN, 256>>>(N);
    proj_kernel<<<(N + NPB - 1) / NPB, 128>>>(x, Wq, Wk, Wl, bl, N);
    hist_kernel<<<(E + 255) / 256, 256>>>(rows, E);
    scan1_kernel<<<nblocksN, 256>>>(N);
    scan2_kernel<<<1, 256>>>(nblocksN);
    scan3_kernel<<<nblocksN, 256>>>(N, E);
    scatter_kernel<<<(E + 255) / 256, 256>>>(rows, cols, E);
    qagg_csr_kernel<<<(N * 32 + 255) / 256, 256>>>(N);
    attn_agg_kernel<<<(N * 32 + 255) / 256, 256>>>(out, N);
}

// round 5
// speedup vs baseline: 1.0155x; 1.0155x over previous
#include <cuda_runtime.h>
#include <cstdint>

#define IN_DIM  128
#define OUT_DIM 128
#define NHEADS  4
#define NEG_SLOPE 0.2f

#define N_MAX 50000
#define E_MAX 1600000
#define FULL 0xFFFFFFFFu
#define MAXC 4   // cached score strips: covers deg <= 128

// -------- device scratch (static: no allocation allowed) --------
__device__ float g_hq   [N_MAX * NHEADS];
__device__ float g_kact [N_MAX * NHEADS];
__device__ float g_qagg [N_MAX * NHEADS];
__device__ float g_hproj[(size_t)N_MAX * OUT_DIM];
__device__ float g_alpha[E_MAX];
__device__ int   g_cnt  [N_MAX];
__device__ int   g_off  [N_MAX + 1];
__device__ int   g_pos  [N_MAX];
__device__ int   g_bsum [256];
__device__ int   g_csr_col[E_MAX];

// ================= kernel 0: init (zero histogram) =================
__global__ __launch_bounds__(256) void init_kernel(int N) {
    int i = blockIdx.x * 256 + threadIdx.x;
    if (i < N) g_cnt[i] = 0;
}

// ================= kernel 1: projections =================
#define NPB 16
__global__ __launch_bounds__(128) void proj_kernel(
    const float* __restrict__ x,
    const float* __restrict__ Wq, const float* __restrict__ Wk,
    const float* __restrict__ Wl, const float* __restrict__ bl, int N)
{
    __shared__ float xs[NPB * IN_DIM];
    const int t = threadIdx.x;
    const int base = blockIdx.x * NPB;
    const int nn = min(NPB, N - base);
    if (nn <= 0) return;

    {
        const float4* xg = (const float4*)(x + (size_t)base * IN_DIM);
        float4* xs4 = (float4*)xs;
        const int tot4 = nn * (IN_DIM / 4);
        for (int i = t; i < tot4; i += 128) xs4[i] = xg[i];
    }
    __syncthreads();

    // per-head q/k projections: t = n2*8 + h
    {
        const int n2 = t >> 3;
        const int h  = t & 7;
        if (n2 < nn) {
            const float* wrow = (h < 4) ? (Wq + h * IN_DIM) : (Wk + (h - 4) * IN_DIM);
            const float4* w4 = (const float4*)wrow;
            const float4* xr = (const float4*)(xs + n2 * IN_DIM);
            float d = 0.0f;
            #pragma unroll
            for (int k = 0; k < IN_DIM / 4; k++) {
                float4 w = w4[k]; float4 xv = xr[k];
                d += w.x * xv.x + w.y * xv.y + w.z * xv.z + w.w * xv.w;
            }
            const int node = base + n2;
            if (h < 4) g_hq[node * NHEADS + h] = d;
            else       g_kact[node * NHEADS + (h - 4)] = (d >= 0.0f) ? d : NEG_SLOPE * d;
        }
    }

    float acc[NPB];
    #pragma unroll
    for (int n = 0; n < NPB; n++) acc[n] = 0.0f;

    const float4* wl4 = (const float4*)(Wl + (size_t)t * IN_DIM);
    #pragma unroll 4
    for (int k = 0; k < IN_DIM / 4; k++) {
        float4 w = wl4[k];
        #pragma unroll
        for (int n = 0; n < NPB; n++) {
            float4 xv = ((const float4*)(xs + n * IN_DIM))[k];
            acc[n] += w.x * xv.x + w.y * xv.y + w.z * xv.z + w.w * xv.w;
        }
    }
    const float b = bl[t];
    for (int n = 0; n < nn; n++)
        g_hproj[(size_t)(base + n) * OUT_DIM + t] = acc[n] + b;
}

// ================= kernel 2: histogram of rows =================
__global__ __launch_bounds__(256) void hist_kernel(const int* __restrict__ rows, int E) {
    int e = blockIdx.x * 256 + threadIdx.x;
    if (e < E) atomicAdd(&g_cnt[rows[e]], 1);
}

// ================= scan (3 stages) =================
__device__ __forceinline__ int warp_incl_scan(int v, int lane) {
    #pragma unroll
    for (int d = 1; d < 32; d <<= 1) {
        int t = __shfl_up_sync(FULL, v, d);
        if (lane >= d) v += t;
    }
    return v;
}

__global__ __launch_bounds__(256) void scan1_kernel(int N) {
    int i = blockIdx.x * 256 + threadIdx.x;
    int lane = threadIdx.x & 31, wid = threadIdx.x >> 5;
    int v = (i < N) ? g_cnt[i] : 0;
    int s = warp_incl_scan(v, lane);
    __shared__ int wsum[8];
    if (lane == 31) wsum[wid] = s;
    __syncthreads();
    if (wid == 0) {
        int ws = (lane < 8) ? wsum[lane] : 0;
        #pragma unroll
        for (int d = 1; d < 8; d <<= 1) {
            int t = __shfl_up_sync(FULL, ws, d);
            if (lane >= d) ws += t;
        }
        if (lane < 8) wsum[lane] = ws;
    }
    __syncthreads();
    int excl = s - v + (wid > 0 ? wsum[wid - 1] : 0);
    if (i < N) g_off[i] = excl;
    if (threadIdx.x == 255) g_bsum[blockIdx.x] = excl + v;
}

__global__ __launch_bounds__(256) void scan2_kernel(int nb) {
    int i = threadIdx.x;
    int lane = i & 31, wid = i >> 5;
    int v = (i < nb) ? g_bsum[i] : 0;
    int s = warp_incl_scan(v, lane);
    __shared__ int wsum[8];
    if (lane == 31) wsum[wid] = s;
    __syncthreads();
    if (wid == 0) {
        int ws = (lane < 8) ? wsum[lane] : 0;
        #pragma unroll
        for (int d = 1; d < 8; d <<= 1) {
            int t = __shfl_up_sync(FULL, ws, d);
            if (lane >= d) ws += t;
        }
        if (lane < 8) wsum[lane] = ws;
    }
    __syncthreads();
    int excl = s - v + (wid > 0 ? wsum[wid - 1] : 0);
    if (i < nb) g_bsum[i] = excl;
}

__global__ __launch_bounds__(256) void scan3_kernel(int N, int E) {
    int i = blockIdx.x * 256 + threadIdx.x;
    if (i < N) {
        int o = g_off[i] + g_bsum[i >> 8];
        g_off[i] = o;
        g_pos[i] = o;
    }
    if (i == 0) g_off[N] = E;
}

// ================= kernel: scatter edges into CSR =================
__global__ __launch_bounds__(256) void scatter_kernel(
    const int* __restrict__ rows, const int* __restrict__ cols, int E)
{
    int e = blockIdx.x * 256 + threadIdx.x;
    if (e >= E) return;
    int r = rows[e];
    int p = atomicAdd(&g_pos[r], 1);
    g_csr_col[p] = cols[e];
}

// ================= kernel: q_agg via CSR (no atomics) =================
__global__ __launch_bounds__(256) void qagg_csr_kernel(int N) {
    int w = (blockIdx.x * 256 + threadIdx.x) >> 5;
    int lane = threadIdx.x & 31;
    if (w >= N) return;
    int beg = g_off[w], end = g_off[w + 1];
    float4 acc = {0.f, 0.f, 0.f, 0.f};
    for (int e = beg + lane; e < end; e += 32) {
        int c = __ldg(g_csr_col + e);
        float4 v = __ldg(((const float4*)g_hq) + c);
        acc.x += v.x; acc.y += v.y; acc.z += v.z; acc.w += v.w;
    }
    #pragma unroll
    for (int d = 16; d; d >>= 1) {
        acc.x += __shfl_xor_sync(FULL, acc.x, d);
        acc.y += __shfl_xor_sync(FULL, acc.y, d);
        acc.z += __shfl_xor_sync(FULL, acc.z, d);
        acc.w += __shfl_xor_sync(FULL, acc.w, d);
    }
    if (lane == 0) ((float4*)g_qagg)[w] = acc;
}

// ================= softmax + per-edge alpha (warp per node) ==========
__global__ __launch_bounds__(256) void softmax_alpha_kernel(int N) {
    int node = (blockIdx.x * 256 + threadIdx.x) >> 5;
    int lane = threadIdx.x & 31;
    if (node >= N) return;
    const int beg = g_off[node], end = g_off[node + 1];
    const int deg = end - beg;
    if (deg == 0) return;

    const float4 ka = ((const float4*)g_kact)[node];
    const int nstr = (deg + 31) >> 5;

    if (nstr <= MAXC) {
        // ---- fast path: cache scores in registers (ONE q-gather pass)
        float4 sc[MAXC];
        float4 mx = {-3.4e38f, -3.4e38f, -3.4e38f, -3.4e38f};
        #pragma unroll
        for (int s = 0; s < MAXC; s++) {
            sc[s] = make_float4(0.f, 0.f, 0.f, 0.f);
            if (s < nstr) {
                int e = beg + s * 32 + lane;
                if (e < end) {
                    int c = __ldg(g_csr_col + e);
                    float4 q = __ldg(((const float4*)g_qagg) + c);
                    sc[s].x = ka.x * q.x; sc[s].y = ka.y * q.y;
                    sc[s].z = ka.z * q.z; sc[s].w = ka.w * q.w;
                    mx.x = fmaxf(mx.x, sc[s].x); mx.y = fmaxf(mx.y, sc[s].y);
                    mx.z = fmaxf(mx.z, sc[s].z); mx.w = fmaxf(mx.w, sc[s].w);
                }
            }
        }
        #pragma unroll
        for (int d = 16; d; d >>= 1) {
            mx.x = fmaxf(mx.x, __shfl_xor_sync(FULL, mx.x, d));
            mx.y = fmaxf(mx.y, __shfl_xor_sync(FULL, mx.y, d));
            mx.z = fmaxf(mx.z, __shfl_xor_sync(FULL, mx.z, d));
            mx.w = fmaxf(mx.w, __shfl_xor_sync(FULL, mx.w, d));
        }
        float4 sm = {0.f, 0.f, 0.f, 0.f};
        #pragma unroll
        for (int s = 0; s < MAXC; s++) {
            if (s < nstr) {
                int e = beg + s * 32 + lane;
                if (e < end) {
                    sc[s].x = __expf(sc[s].x - mx.x);
                    sc[s].y = __expf(sc[s].y - mx.y);
                    sc[s].z = __expf(sc[s].z - mx.z);
                    sc[s].w = __expf(sc[s].w - mx.w);
                    sm.x += sc[s].x; sm.y += sc[s].y; sm.z += sc[s].z; sm.w += sc[s].w;
                }
            }
        }
        #pragma unroll
        for (int d = 16; d; d >>= 1) {
            sm.x += __shfl_xor_sync(FULL, sm.x, d);
            sm.y += __shfl_xor_sync(FULL, sm.y, d);
            sm.z += __shfl_xor_sync(FULL, sm.z, d);
            sm.w += __shfl_xor_sync(FULL, sm.w, d);
        }
        float4 inv;
        inv.x = 0.25f * __fdividef(1.0f, sm.x + 1e-8f);
        inv.y = 0.25f * __fdividef(1.0f, sm.y + 1e-8f);
        inv.z = 0.25f * __fdividef(1.0f, sm.z + 1e-8f);
        inv.w = 0.25f * __fdividef(1.0f, sm.w + 1e-8f);
        #pragma unroll
        for (int s = 0; s < MAXC; s++) {
            if (s < nstr) {
                int e = beg + s * 32 + lane;
                if (e < end)
                    g_alpha[e] = sc[s].x * inv.x + sc[s].y * inv.y
                               + sc[s].z * inv.z + sc[s].w * inv.w;
            }
        }
    } else {
        // ---- fallback (deg > 128): two gather passes
        float4 mx = {-3.4e38f, -3.4e38f, -3.4e38f, -3.4e38f};
        for (int e = beg + lane; e < end; e += 32) {
            int c = __ldg(g_csr_col + e);
            float4 q = __ldg(((const float4*)g_qagg) + c);
            mx.x = fmaxf(mx.x, ka.x * q.x);
            mx.y = fmaxf(mx.y, ka.y * q.y);
            mx.z = fmaxf(mx.z, ka.z * q.z);
            mx.w = fmaxf(mx.w, ka.w * q.w);
        }
        #pragma unroll
        for (int d = 16; d; d >>= 1) {
            mx.x = fmaxf(mx.x, __shfl_xor_sync(FULL, mx.x, d));
            mx.y = fmaxf(mx.y, __shfl_xor_sync(FULL, mx.y, d));
            mx.z = fmaxf(mx.z, __shfl_xor_sync(FULL, mx.z, d));
            mx.w = fmaxf(mx.w, __shfl_xor_sync(FULL, mx.w, d));
        }
        float4 sm = {0.f, 0.f, 0.f, 0.f};
        for (int e = beg + lane; e < end; e += 32) {
            int c = __ldg(g_csr_col + e);
            float4 q = __ldg(((const float4*)g_qagg) + c);
            sm.x += __expf(ka.x * q.x - mx.x);
            sm.y += __expf(ka.y * q.y - mx.y);
            sm.z += __expf(ka.z * q.z - mx.z);
            sm.w += __expf(ka.w * q.w - mx.w);
        }
        #pragma unroll
        for (int d = 16; d; d >>= 1) {
            sm.x += __shfl_xor_sync(FULL, sm.x, d);
            sm.y += __shfl_xor_sync(FULL, sm.y, d);
            sm.z += __shfl_xor_sync(FULL, sm.z, d);
            sm.w += __shfl_xor_sync(FULL, sm.w, d);
        }
        float4 inv;
        inv.x = 0.25f * __fdividef(1.0f, sm.x + 1e-8f);
        inv.y = 0.25f * __fdividef(1.0f, sm.y + 1e-8f);
        inv.z = 0.25f * __fdividef(1.0f, sm.z + 1e-8f);
        inv.w = 0.25f * __fdividef(1.0f, sm.w + 1e-8f);
        for (int e = beg + lane; e < end; e += 32) {
            int c = __ldg(g_csr_col + e);
            float4 q = __ldg(((const float4*)g_qagg) + c);
            g_alpha[e] = __expf(ka.x * q.x - mx.x) * inv.x
                       + __expf(ka.y * q.y - mx.y) * inv.y
                       + __expf(ka.z * q.z - mx.z) * inv.z
                       + __expf(ka.w * q.w - mx.w) * inv.w;
        }
    }
}

// ========== aggregation: warp per (node, 64-dim half) ==========
__global__ __launch_bounds__(256) void agg_kernel(float* __restrict__ out, int N) {
    int w = (blockIdx.x * 256 + threadIdx.x) >> 5;
    int lane = threadIdx.x & 31;
    int node = w >> 1;
    int half = w & 1;
    if (node >= N) return;
    const int beg = g_off[node], end = g_off[node + 1];

    float2* outp = ((float2*)out) + (size_t)node * 64 + half * 32 + lane;
    if (beg == end) { *outp = make_float2(0.f, 0.f); return; }

    const float2* hp = ((const float2*)g_hproj) + half * 32 + lane;
    float2 acc = {0.f, 0.f};
    for (int base = beg; base < end; base += 32) {
        int e = base + lane;
        float a = 0.0f; int c = 0;
        if (e < end) {
            a = __ldg(g_alpha + e);
            c = __ldg(g_csr_col + e);
        }
        int cnt = min(32, end - base);
        #pragma unroll 8
        for (int j = 0; j < 32; j++) {
            if (j >= cnt) break;
            float aj = __shfl_sync(FULL, a, j);
            int   cj = __shfl_sync(FULL, c, j);
            float2 v = __ldg(hp + (size_t)cj * 64);
            acc.x = fmaf(aj, v.x, acc.x);
            acc.y = fmaf(aj, v.y, acc.y);
        }
    }
    acc.x = (acc.x >= 0.f) ? acc.x : NEG_SLOPE * acc.x;
    acc.y = (acc.y >= 0.f) ? acc.y : NEG_SLOPE * acc.y;
    *outp = acc;
}

// ================= launch =================
extern "C" void kernel_launch(void* const* d_in, const int* in_sizes, int n_in,
                              void* d_out, int out_size)
{
    const float* x  = (const float*)d_in[0];
    const int*   ei = (const int*)d_in[1];
    const float* Wq = (const float*)d_in[2];
    const float* Wk = (const float*)d_in[3];
    const float* Wl = (const float*)d_in[4];
    const float* bl = (const float*)d_in[5];
    float* out = (float*)d_out;

    const int N = in_sizes[0] / IN_DIM;
    const int E = in_sizes[1] / 2;
    const int* rows = ei;
    const int* cols = ei + E;
    const int nblocksN = (N + 255) / 256;

    init_kernel<<<nblocksN, 256>>>(N);
    proj_kernel<<<(N + NPB - 1) / NPB, 128>>>(x, Wq, Wk, Wl, bl, N);
    hist_kernel<<<(E + 255) / 256, 256>>>(rows, E);
    scan1_kernel<<<nblocksN, 256>>>(N);
    scan2_kernel<<<1, 256>>>(nblocksN);
    scan3_kernel<<<nblocksN, 256>>>(N, E);
    scatter_kernel<<<(E + 255) / 256, 256>>>(rows, cols, E);
    qagg_csr_kernel<<<(N * 32 + 255) / 256, 256>>>(N);
    softmax_alpha_kernel<<<(N * 32 + 255) / 256, 256>>>(N);
    agg_kernel<<<(2 * N * 32 + 255) / 256, 256>>>(out, N);
}